// round 2
// baseline (speedup 1.0000x reference)
#include <cuda_runtime.h>
#include <cstdint>

#define VOCAB 50257
#define BATCH 4096

// Per-row loss scratch (deterministic two-kernel reduction; no device mallocs).
__device__ float g_row_loss[BATCH];

__global__ __launch_bounds__(256) void ce_row_kernel(
    const float* __restrict__ pred,
    const int* __restrict__ y)   // JAX default x64-disabled => int32 labels
{
    const int row = blockIdx.x;
    const float* __restrict__ p = pred + (size_t)row * VOCAB;
    const int tid = threadIdx.x;
    const int T = 256;

    // Row base misalignment (in floats) relative to 16B; prologue to align.
    const int mis = (int)(((uintptr_t)p & 15u) >> 2);
    const int pro = (4 - mis) & 3;

    float s = 0.f;

    if (tid < pro) s += __expf(p[tid]);

    const float4* __restrict__ p4 = (const float4*)(p + pro);
    const int n4 = (VOCAB - pro) >> 2;

    // Main vectorized loop: LDG.128 + 4x EX2. Unroll for MLP.
    int i = tid;
    #pragma unroll 4
    for (; i < n4; i += T) {
        float4 v = p4[i];
        s += __expf(v.x);
        s += __expf(v.y);
        s += __expf(v.z);
        s += __expf(v.w);
    }

    const int done = pro + (n4 << 2);
    const int tail = VOCAB - done;
    if (tid < tail) s += __expf(p[done + tid]);

    // Block reduction (fixed order -> deterministic).
    __shared__ float sm[8];
    #pragma unroll
    for (int o = 16; o > 0; o >>= 1)
        s += __shfl_xor_sync(0xffffffffu, s, o);
    const int wid = tid >> 5;
    const int lid = tid & 31;
    if (lid == 0) sm[wid] = s;
    __syncthreads();
    if (wid == 0) {
        float v = (lid < 8) ? sm[lid] : 0.f;
        #pragma unroll
        for (int o = 16; o > 0; o >>= 1)
            v += __shfl_xor_sync(0xffffffffu, v, o);
        if (lid == 0) {
            const int t = y[row];
            // loss_row = log(sum_j exp(p_j)) - p[y]
            g_row_loss[row] = __logf(v) - p[t];
        }
    }
}

__global__ __launch_bounds__(1024) void ce_reduce_kernel(float* __restrict__ out)
{
    const int tid = threadIdx.x;
    float s = 0.f;
    #pragma unroll
    for (int i = tid; i < BATCH; i += 1024) s += g_row_loss[i];

    #pragma unroll
    for (int o = 16; o > 0; o >>= 1)
        s += __shfl_xor_sync(0xffffffffu, s, o);

    __shared__ float sm[32];
    const int wid = tid >> 5;
    const int lid = tid & 31;
    if (lid == 0) sm[wid] = s;
    __syncthreads();
    if (wid == 0) {
        float v = sm[lid];
        #pragma unroll
        for (int o = 16; o > 0; o >>= 1)
            v += __shfl_xor_sync(0xffffffffu, v, o);
        if (lid == 0) out[0] = v * (1.0f / BATCH);
    }
}

extern "C" void kernel_launch(void* const* d_in, const int* in_sizes, int n_in,
                              void* d_out, int out_size)
{
    const float* pred = (const float*)d_in[0];
    const int* y = (const int*)d_in[1];
    float* out = (float*)d_out;

    ce_row_kernel<<<BATCH, 256>>>(pred, y);
    ce_reduce_kernel<<<1, 1024>>>(out);
}

// round 3
// speedup vs baseline: 1.0059x; 1.0059x over previous
#include <cuda_runtime.h>
#include <cstdint>

#define VOCAB 50257
#define BATCH 4096

// Scratch for per-row losses + completion counter (no device mallocs).
__device__ float g_row_loss[BATCH];
__device__ unsigned int g_done = 0;   // self-resetting each launch

__global__ __launch_bounds__(256) void ce_fused_kernel(
    const float* __restrict__ pred,
    const int* __restrict__ y,       // JAX x64-disabled => int32 labels
    float* __restrict__ out)
{
    const int row = blockIdx.x;
    const float* __restrict__ p = pred + (size_t)row * VOCAB;
    const int tid = threadIdx.x;
    const int T = 256;

    // Row base misalignment (in floats) relative to 16B; prologue to align.
    const int mis = (int)(((uintptr_t)p & 15u) >> 2);
    const int pro = (4 - mis) & 3;

    float s0 = 0.f, s1 = 0.f;

    if (tid < pro) s0 += __expf(p[tid]);

    const float4* __restrict__ p4 = (const float4*)(p + pro);
    const int n4 = (VOCAB - pro) >> 2;

    // Main loop: streaming LDG.128 (evict-first) + 4x EX2. Deep unroll for MLP.
    int i = tid;
    #pragma unroll 8
    for (; i < n4; i += T) {
        float4 v = __ldcs(&p4[i]);
        s0 += __expf(v.x);
        s1 += __expf(v.y);
        s0 += __expf(v.z);
        s1 += __expf(v.w);
    }

    const int done = pro + (n4 << 2);
    const int tail = VOCAB - done;
    if (tid < tail) s1 += __expf(p[done + tid]);

    float s = s0 + s1;

    // Block reduction (fixed order -> deterministic).
    __shared__ float sm[8];
    #pragma unroll
    for (int o = 16; o > 0; o >>= 1)
        s += __shfl_xor_sync(0xffffffffu, s, o);
    const int wid = tid >> 5;
    const int lid = tid & 31;
    if (lid == 0) sm[wid] = s;
    __syncthreads();

    __shared__ bool is_last;
    if (tid == 0) {
        float v = sm[0] + sm[1] + sm[2] + sm[3] + sm[4] + sm[5] + sm[6] + sm[7];
        const int t = y[row];
        // loss_row = log(sum_j exp(p_j)) - p[y]
        g_row_loss[row] = __logf(v) - p[t];
        __threadfence();
        unsigned int prev = atomicAdd(&g_done, 1u);
        is_last = (prev == (unsigned)(BATCH - 1));
    }
    __syncthreads();

    // Last block to finish reduces all row losses (data fresh in L2).
    if (is_last) {
        float r = 0.f;
        #pragma unroll
        for (int k = 0; k < BATCH / 256; k++)
            r += g_row_loss[tid + k * 256];

        #pragma unroll
        for (int o = 16; o > 0; o >>= 1)
            r += __shfl_xor_sync(0xffffffffu, r, o);
        if (lid == 0) sm[wid] = r;
        __syncthreads();
        if (tid == 0) {
            float tot = sm[0] + sm[1] + sm[2] + sm[3] + sm[4] + sm[5] + sm[6] + sm[7];
            out[0] = tot * (1.0f / BATCH);
            g_done = 0;   // reset for next launch / graph replay
        }
    }
}

extern "C" void kernel_launch(void* const* d_in, const int* in_sizes, int n_in,
                              void* d_out, int out_size)
{
    const float* pred = (const float*)d_in[0];
    const int* y = (const int*)d_in[1];
    float* out = (float*)d_out;

    ce_fused_kernel<<<BATCH, 256>>>(pred, y, out);
}